// round 1
// baseline (speedup 1.0000x reference)
#include <cuda_runtime.h>
#include <math.h>

// ---------------------------------------------------------------------------
// HardNegativeContrastiveLoss, N=8192, D=256 fixed (D hardcoded), fp32.
//
// loss = 0.5 * ( mean_r CE_row(logits)      // logits = img @ cur^T / T
//              + mean_r CE_row(logits^T) )  // logits^T = cur @ img^T / T
// CE_row = logsumexp([pos_r, top32(row \ diag)]) - pos_r
//
// Strategy: fused GEMM + streaming top-k, run twice with swapped operands.
// Per CTA: 64 rows persist in SMEM, iterate 64-col blocks over all 8192 cols,
// 4x4 register microtile, spill 64x64 tile to SMEM, 64 row-owner threads
// maintain sorted top-32 per row. No logit materialization in HBM.
// ---------------------------------------------------------------------------

#define BM 64
#define BN 64
#define BK 32
#define DIM 256
#define NTHREADS 256

#define AS_STRIDE 260   // 256 + 4 pad (float4-friendly, conflict-free reads)
#define BS_STRIDE 33    // 32 + 1 pad (conflict-free col-major reads)
#define TL_STRIDE 69    // 64 + 5 pad (conflict-free row scans)

// floats of dynamic smem
#define SM_AS     0
#define SM_BS     (SM_AS + BM * AS_STRIDE)
#define SM_TL     (SM_BS + BN * BS_STRIDE)
#define SM_TK     (SM_TL + BM * TL_STRIDE)
#define SM_PS     (SM_TK + BM * 32)
#define SM_RL     (SM_PS + BM)
#define SM_TOTAL  (SM_RL + BM)

__device__ float g_partial[1024];

__global__ __launch_bounds__(NTHREADS, 1)
void pass_kernel(const float* __restrict__ A, const float* __restrict__ B,
                 int partialBase, int N) {
    extern __shared__ float sm[];
    float* As = sm + SM_AS;
    float* Bs = sm + SM_BS;
    float* Tl = sm + SM_TL;
    float* Tk = sm + SM_TK;
    float* Ps = sm + SM_PS;
    float* Rl = sm + SM_RL;

    const int tid = threadIdx.x;
    const int tx = tid & 15;          // 16 col-groups
    const int ty = tid >> 4;          // 16 row-groups
    const int r0 = ty * 4;
    const int c0 = tx * 4;
    const int rowBase = blockIdx.x * BM;

    // ---- load persistent A rows: 64 x 256 floats, float4, coalesced ----
    {
        const float4* A4 = reinterpret_cast<const float4*>(A + (size_t)rowBase * DIM);
        for (int idx = tid; idx < BM * (DIM / 4); idx += NTHREADS) {
            int r = idx >> 6;         // /64
            int k4 = idx & 63;
            float4 v = A4[r * (DIM / 4) + k4];
            *reinterpret_cast<float4*>(&As[r * AS_STRIDE + k4 * 4]) = v;
        }
    }
    // ---- init top-k to -inf ----
    for (int idx = tid; idx < BM * 32; idx += NTHREADS) Tk[idx] = -INFINITY;
    __syncthreads();

    const int numCB = N / BN;
    for (int cb = 0; cb < numCB; ++cb) {
        const int colBase = cb * BN;
        float acc[4][4];
        #pragma unroll
        for (int i = 0; i < 4; ++i)
            #pragma unroll
            for (int j = 0; j < 4; ++j) acc[i][j] = 0.0f;

        for (int kc = 0; kc < DIM; kc += BK) {
            __syncthreads();   // Bs safe to overwrite
            {   // load B chunk: 64 cols x 32 k, coalesced (k = lane)
                int k = tid & 31;
                int c = tid >> 5;          // 0..7
                const float* Bp = B + (size_t)(colBase + c) * DIM + kc + k;
                #pragma unroll
                for (int cc = 0; cc < BN; cc += 8) {
                    Bs[(c + cc) * BS_STRIDE + k] = Bp[(size_t)cc * DIM];
                }
            }
            __syncthreads();
            #pragma unroll
            for (int kk = 0; kk < BK; ++kk) {
                float a0 = As[(r0 + 0) * AS_STRIDE + kc + kk];
                float a1 = As[(r0 + 1) * AS_STRIDE + kc + kk];
                float a2 = As[(r0 + 2) * AS_STRIDE + kc + kk];
                float a3 = As[(r0 + 3) * AS_STRIDE + kc + kk];
                float b0 = Bs[(c0 + 0) * BS_STRIDE + kk];
                float b1 = Bs[(c0 + 1) * BS_STRIDE + kk];
                float b2 = Bs[(c0 + 2) * BS_STRIDE + kk];
                float b3 = Bs[(c0 + 3) * BS_STRIDE + kk];
                acc[0][0] += a0 * b0; acc[0][1] += a0 * b1; acc[0][2] += a0 * b2; acc[0][3] += a0 * b3;
                acc[1][0] += a1 * b0; acc[1][1] += a1 * b1; acc[1][2] += a1 * b2; acc[1][3] += a1 * b3;
                acc[2][0] += a2 * b0; acc[2][1] += a2 * b1; acc[2][2] += a2 * b2; acc[2][3] += a2 * b3;
                acc[3][0] += a3 * b0; acc[3][1] += a3 * b1; acc[3][2] += a3 * b2; acc[3][3] += a3 * b3;
            }
        }
        __syncthreads();   // all compute done before tile write (tile was read by prev top-k)
        #pragma unroll
        for (int i = 0; i < 4; ++i)
            #pragma unroll
            for (int j = 0; j < 4; ++j)
                Tl[(r0 + i) * TL_STRIDE + c0 + j] = acc[i][j];
        __syncthreads();

        // ---- streaming top-32 update, one thread per row ----
        if (tid < BM) {
            const int r = tid;
            const int grow = rowBase + r;
            float* tk = &Tk[r * 32];
            float thr = tk[31];
            #pragma unroll 4
            for (int j = 0; j < BN; ++j) {
                float v = Tl[r * TL_STRIDE + j];
                int col = colBase + j;
                if (col == grow) { Ps[r] = v; continue; }
                if (v > thr) {
                    int p = 31;
                    while (p > 0 && tk[p - 1] < v) { tk[p] = tk[p - 1]; --p; }
                    tk[p] = v;
                    thr = tk[31];
                }
            }
        }
        // next cb's first __syncthreads() fences the top-k before Bs/Tl reuse
    }
    __syncthreads();

    // ---- per-row loss ----
    if (tid < BM) {
        const float invT = 1.0f / 0.07f;
        const float* tk = &Tk[tid * 32];
        float p = Ps[tid] * invT;
        float m = fmaxf(p, tk[0] * invT);   // tk[0] is the max of the 32
        float s = expf(p - m);
        #pragma unroll
        for (int i = 0; i < 32; ++i) s += expf(tk[i] * invT - m);
        Rl[tid] = m + logf(s) - p;
    }
    __syncthreads();
    if (tid == 0) {
        float sum = 0.0f;
        for (int r = 0; r < BM; ++r) sum += Rl[r];   // fixed order: deterministic
        g_partial[partialBase + blockIdx.x] = sum;
    }
}

__global__ void finalize_kernel(float* out, int n, float scale) {
    if (threadIdx.x == 0) {
        float sum = 0.0f;
        for (int i = 0; i < n; ++i) sum += g_partial[i];
        out[0] = sum * scale;
    }
}

extern "C" void kernel_launch(void* const* d_in, const int* in_sizes, int n_in,
                              void* d_out, int out_size) {
    const float* img = (const float*)d_in[0];
    const float* cur = (const float*)d_in[1];
    float* out = (float*)d_out;

    const int N = in_sizes[0] / DIM;       // 8192
    const int grid = N / BM;               // 128
    const size_t smem = SM_TOTAL * sizeof(float);

    cudaFuncSetAttribute(pass_kernel, cudaFuncAttributeMaxDynamicSharedMemorySize, (int)smem);

    // pass 1: rows of logits  (img @ cur^T)
    pass_kernel<<<grid, NTHREADS, smem>>>(img, cur, 0, N);
    // pass 2: rows of logits^T (cur @ img^T)
    pass_kernel<<<grid, NTHREADS, smem>>>(cur, img, grid, N);
    // loss = (sum1 + sum2) / (2N)
    finalize_kernel<<<1, 1>>>(out, 2 * grid, 0.5f / (float)N);
}

// round 2
// speedup vs baseline: 2.6813x; 2.6813x over previous
#include <cuda_runtime.h>
#include <cuda_bf16.h>
#include <math.h>
#include <stdint.h>

// ---------------------------------------------------------------------------
// HardNegativeContrastiveLoss, N=8192, D=256, fp32 in -> scalar fp32.
// Round 2: bf16 tensor-core (mma.sync m16n8k16) fused GEMM + streaming top-32.
// Both directions run concurrently in one 128-CTA launch (one wave).
// Logits never touch HBM; B panels are L2-resident (4 MB per matrix).
// ---------------------------------------------------------------------------

#define NROWS 8192
#define DIM   256
#define BM    128
#define BN    128
#define NTH   256
#define AS_STRIDE 264   // bf16 elems/row = 528 B  (528 mod 128 = 16 -> LDSM conflict-free)
#define TLS   132       // float elems/row = 528 B (aliases Bs exactly)

__device__ __nv_bfloat16 g_bf[2 * NROWS * DIM];   // [img ; cur] in bf16
__device__ float g_partial[128];

// ---- fp32 -> bf16 conversion for both inputs ------------------------------
__global__ void convert_kernel(const float* __restrict__ a, const float* __restrict__ b) {
    int i = blockIdx.x * blockDim.x + threadIdx.x;
    const int n = NROWS * DIM / 4;
    if (i < n) {
        float4 v = ((const float4*)a)[i];
        __nv_bfloat162* o = (__nv_bfloat162*)(g_bf) + i * 2;
        o[0] = __floats2bfloat162_rn(v.x, v.y);
        o[1] = __floats2bfloat162_rn(v.z, v.w);
    } else if (i < 2 * n) {
        int j = i - n;
        float4 v = ((const float4*)b)[j];
        __nv_bfloat162* o = (__nv_bfloat162*)(g_bf + NROWS * DIM) + j * 2;
        o[0] = __floats2bfloat162_rn(v.x, v.y);
        o[1] = __floats2bfloat162_rn(v.z, v.w);
    }
}

// ---- PTX helpers ----------------------------------------------------------
__device__ __forceinline__ void ldsm4(uint32_t& r0, uint32_t& r1, uint32_t& r2, uint32_t& r3,
                                      uint32_t addr) {
    asm volatile("ldmatrix.sync.aligned.m8n8.x4.shared.b16 {%0,%1,%2,%3}, [%4];"
                 : "=r"(r0), "=r"(r1), "=r"(r2), "=r"(r3) : "r"(addr));
}

__device__ __forceinline__ void mma16816(float* c,
                                         uint32_t a0, uint32_t a1, uint32_t a2, uint32_t a3,
                                         uint32_t b0, uint32_t b1) {
    asm volatile("mma.sync.aligned.m16n8k16.row.col.f32.bf16.bf16.f32 "
                 "{%0,%1,%2,%3}, {%4,%5,%6,%7}, {%8,%9}, {%0,%1,%2,%3};"
                 : "+f"(c[0]), "+f"(c[1]), "+f"(c[2]), "+f"(c[3])
                 : "r"(a0), "r"(a1), "r"(a2), "r"(a3), "r"(b0), "r"(b1));
}

// ---- fused GEMM + top-32 + loss -------------------------------------------
__global__ __launch_bounds__(NTH, 1)
void pass_kernel() {
    extern __shared__ char smraw[];
    __nv_bfloat16* As = (__nv_bfloat16*)smraw;
    __nv_bfloat16* Bs = As + BM * AS_STRIDE;
    float* Tl = (float*)Bs;                        // spill tile aliases Bs
    float* Tk = (float*)(Bs + BM * AS_STRIDE);     // [128][32] sorted desc
    float* Ps = Tk + BM * 32;                      // positive logits
    float* Rl = Ps + BM;                           // per-row losses

    const int tid  = threadIdx.x;
    const int lane = tid & 31;
    const int w    = tid >> 5;                     // 8 warps, warp w owns rows [16w,16w+16)
    const int pass = blockIdx.x >> 6;              // 0: img@cur^T rows, 1: cur@img^T rows
    const int rowBlock = blockIdx.x & 63;
    const int rowBase  = rowBlock * BM;

    const __nv_bfloat16* Asrc = g_bf + (size_t)pass       * NROWS * DIM;
    const __nv_bfloat16* Bsrc = g_bf + (size_t)(1 - pass) * NROWS * DIM;

    // ---- load persistent A rows (128 x 256 bf16) ----
    {
        const uint4* src = (const uint4*)(Asrc + (size_t)rowBase * DIM);
        for (int idx = tid; idx < BM * (DIM / 8); idx += NTH) {
            int r = idx >> 5, c = idx & 31;        // 32 uint4 per row
            *(uint4*)&As[r * AS_STRIDE + c * 8] = src[r * 32 + c];
        }
    }
    for (int idx = tid; idx < BM * 32; idx += NTH) Tk[idx] = -INFINITY;

    // ldmatrix lane addressing (canonical m16n8k16 frag layouts)
    const uint32_t smA = (uint32_t)__cvta_generic_to_shared(As);
    const uint32_t smB = (uint32_t)__cvta_generic_to_shared(Bs);
    const int aRow     = w * 16 + (lane & 8) + (lane & 7);
    const int aColHalf = (lane & 16) ? 8 : 0;
    const int bRowOff  = ((lane & 16) ? 8 : 0) + (lane & 7);
    const int bColHalf = (lane & 8) ? 8 : 0;

    float acc[16][4];
    #pragma unroll
    for (int nt = 0; nt < 16; ++nt)
        #pragma unroll
        for (int q = 0; q < 4; ++q) acc[nt][q] = 0.0f;

    __syncthreads();

    for (int cb = 0; cb < NROWS / BN; ++cb) {
        // ---- load B panel: 128 cols x 256 k (Bs was free after prior scan) ----
        {
            const uint4* src = (const uint4*)(Bsrc + (size_t)cb * BN * DIM);
            for (int idx = tid; idx < BN * (DIM / 8); idx += NTH) {
                int r = idx >> 5, c = idx & 31;
                *(uint4*)&Bs[r * AS_STRIDE + c * 8] = src[r * 32 + c];
            }
        }
        __syncthreads();

        // ---- 128x128x256 bf16 MMA ----
        #pragma unroll 1
        for (int ks = 0; ks < DIM / 16; ++ks) {
            uint32_t a0, a1, a2, a3;
            ldsm4(a0, a1, a2, a3,
                  smA + (uint32_t)(aRow * AS_STRIDE + ks * 16 + aColHalf) * 2u);
            #pragma unroll
            for (int ntp = 0; ntp < 8; ++ntp) {
                uint32_t b0, b1, b2, b3;
                ldsm4(b0, b1, b2, b3,
                      smB + (uint32_t)((ntp * 16 + bRowOff) * AS_STRIDE + ks * 16 + bColHalf) * 2u);
                mma16816(acc[2 * ntp],     a0, a1, a2, a3, b0, b1);
                mma16816(acc[2 * ntp + 1], a0, a1, a2, a3, b2, b3);
            }
        }
        __syncthreads();   // all warps done reading Bs before it becomes Tl

        // ---- spill accumulators (c frag: c0,c1 -> m=t/4, n=(t%4)*2; c2,c3 -> m+8) ----
        {
            int m0 = w * 16 + (lane >> 2);
            int n0 = (lane & 3) * 2;
            #pragma unroll
            for (int nt = 0; nt < 16; ++nt) {
                int n = nt * 8 + n0;
                *(float2*)&Tl[m0 * TLS + n]       = make_float2(acc[nt][0], acc[nt][1]);
                *(float2*)&Tl[(m0 + 8) * TLS + n] = make_float2(acc[nt][2], acc[nt][3]);
                acc[nt][0] = acc[nt][1] = acc[nt][2] = acc[nt][3] = 0.0f;
            }
        }
        __syncthreads();

        // ---- streaming top-32 update: one thread per row, float4 chunk pre-filter ----
        if (tid < BM) {
            const int r = tid;
            const int grow = rowBase + r;
            const int colBase = cb * BN;
            float* tk = &Tk[r * 32];
            float thr = tk[31];
            const int diagChunk =
                (grow >= colBase && grow < colBase + BN) ? ((grow - colBase) >> 2) : -1;
            for (int ch = 0; ch < BN / 4; ++ch) {
                float4 v = *(float4*)&Tl[r * TLS + ch * 4];
                float mx = fmaxf(fmaxf(v.x, v.y), fmaxf(v.z, v.w));
                if (mx > thr || ch == diagChunk) {
                    float vv[4] = {v.x, v.y, v.z, v.w};
                    #pragma unroll
                    for (int q = 0; q < 4; ++q) {
                        int col = colBase + ch * 4 + q;
                        float val = vv[q];
                        if (col == grow) { Ps[r] = val; continue; }
                        if (val > thr) {
                            int p = 31;
                            while (p > 0 && tk[p - 1] < val) { tk[p] = tk[p - 1]; --p; }
                            tk[p] = val;
                            thr = tk[31];
                        }
                    }
                }
            }
        }
        __syncthreads();   // scan done before Bs reload
    }

    // ---- per-row loss: logsumexp([pos, top32]) - pos ----
    if (tid < BM) {
        const float invT = 1.0f / 0.07f;
        const float* tk = &Tk[tid * 32];
        float p = Ps[tid] * invT;
        float m = fmaxf(p, tk[0] * invT);
        float s = expf(p - m);
        #pragma unroll
        for (int i = 0; i < 32; ++i) s += expf(tk[i] * invT - m);
        Rl[tid] = m + logf(s) - p;
    }
    __syncthreads();
    if (tid == 0) {
        float sum = 0.0f;
        for (int r = 0; r < BM; ++r) sum += Rl[r];   // fixed order: deterministic
        g_partial[blockIdx.x] = sum;
    }
}

__global__ void finalize_kernel(float* out) {
    if (threadIdx.x == 0) {
        float sum = 0.0f;
        for (int i = 0; i < 128; ++i) sum += g_partial[i];
        out[0] = sum * (0.5f / (float)NROWS);
    }
}

extern "C" void kernel_launch(void* const* d_in, const int* in_sizes, int n_in,
                              void* d_out, int out_size) {
    const float* img = (const float*)d_in[0];
    const float* cur = (const float*)d_in[1];
    float* out = (float*)d_out;

    // bf16 conversion: 2 * 8192*256 / 4 float4s
    const int cthreads = 2 * NROWS * DIM / 4;
    convert_kernel<<<(cthreads + 255) / 256, 256>>>(img, cur);

    const size_t smem = (size_t)(2 * BM * AS_STRIDE) * sizeof(__nv_bfloat16)
                      + (size_t)(BM * 32 + BM + BM) * sizeof(float);
    static int configured = 0;
    cudaFuncSetAttribute(pass_kernel, cudaFuncAttributeMaxDynamicSharedMemorySize, (int)smem);
    (void)configured;

    pass_kernel<<<128, NTH, smem>>>();
    finalize_kernel<<<1, 1>>>(out);
}

// round 4
// speedup vs baseline: 6.6593x; 2.4836x over previous
#include <cuda_runtime.h>
#include <cuda_bf16.h>
#include <math.h>
#include <stdint.h>

// ---------------------------------------------------------------------------
// HardNegativeContrastiveLoss N=8192 D=256. Round 4: mma.sync bf16 GEMM
// (tcgen05 unavailable: harness PTX target sm_103 lacks arch-a features)
// + register-level top-k filtering (no tile spill) + cp.async B prefetch.
// Both directions in one 128-CTA wave. Logits never touch HBM.
// ---------------------------------------------------------------------------

#define NROWS 8192
#define DIM   256
#define BM    128
#define BN    64
#define NTH   256
#define NPANEL (NROWS / BN)     // 128
#define STR   264               // bf16 elems per SMEM row (528 B, LDSM conflict-free)

// ---- SMEM byte offsets ----
#define SM_TK    0                        // 128 x 33 f32 sorted desc top-32
#define SM_CNT   16896                    // 128 u32 candidate counts
#define SM_PS    17408                    // 128 f32 positives
#define SM_RL    17920                    // 128 f32 row losses
#define SM_CAND  18432                    // 128 x 69 f32 candidates
#define SM_A     53760                    // 128 x 264 bf16  (67584 B)
#define SM_B0    121344                   // 64 x 264 bf16   (33792 B)
#define SM_B1    155136
#define SM_TOTAL 188928

__device__ __nv_bfloat16 g_bf[2 * NROWS * DIM];
__device__ float g_partial[128];

// ---- fp32 -> bf16 conversion ----------------------------------------------
__global__ void convert_kernel(const float* __restrict__ a, const float* __restrict__ b) {
    int i = blockIdx.x * blockDim.x + threadIdx.x;
    const int n = NROWS * DIM / 4;
    if (i < n) {
        float4 v = ((const float4*)a)[i];
        __nv_bfloat162* o = (__nv_bfloat162*)(g_bf) + i * 2;
        o[0] = __floats2bfloat162_rn(v.x, v.y);
        o[1] = __floats2bfloat162_rn(v.z, v.w);
    } else if (i < 2 * n) {
        int j = i - n;
        float4 v = ((const float4*)b)[j];
        __nv_bfloat162* o = (__nv_bfloat162*)(g_bf + NROWS * DIM) + j * 2;
        o[0] = __floats2bfloat162_rn(v.x, v.y);
        o[1] = __floats2bfloat162_rn(v.z, v.w);
    }
}

// ---- PTX helpers ----------------------------------------------------------
__device__ __forceinline__ void ldsm4(uint32_t& r0, uint32_t& r1, uint32_t& r2, uint32_t& r3,
                                      uint32_t addr) {
    asm volatile("ldmatrix.sync.aligned.m8n8.x4.shared.b16 {%0,%1,%2,%3}, [%4];"
                 : "=r"(r0), "=r"(r1), "=r"(r2), "=r"(r3) : "r"(addr));
}
__device__ __forceinline__ void mma16816(float* c,
                                         uint32_t a0, uint32_t a1, uint32_t a2, uint32_t a3,
                                         uint32_t b0, uint32_t b1) {
    asm volatile("mma.sync.aligned.m16n8k16.row.col.f32.bf16.bf16.f32 "
                 "{%0,%1,%2,%3}, {%4,%5,%6,%7}, {%8,%9}, {%0,%1,%2,%3};"
                 : "+f"(c[0]), "+f"(c[1]), "+f"(c[2]), "+f"(c[3])
                 : "r"(a0), "r"(a1), "r"(a2), "r"(a3), "r"(b0), "r"(b1));
}
__device__ __forceinline__ void cp_async16(uint32_t smem_addr, const void* gptr) {
    asm volatile("cp.async.cg.shared.global [%0], [%1], 16;"
                 :: "r"(smem_addr), "l"(gptr));
}
#define CP_COMMIT() asm volatile("cp.async.commit_group;" ::: "memory")
#define CP_WAIT(N)  asm volatile("cp.async.wait_group " #N ";" ::: "memory")

// ---- fused GEMM + top-32 + loss -------------------------------------------
__global__ __launch_bounds__(NTH, 1)
void pass_kernel() {
    extern __shared__ char smraw[];
    const uint32_t smb = (uint32_t)__cvta_generic_to_shared(smraw);
    float* Tk   = (float*)(smraw + SM_TK);
    unsigned* Cnt = (unsigned*)(smraw + SM_CNT);
    float* Ps   = (float*)(smraw + SM_PS);
    float* Rl   = (float*)(smraw + SM_RL);
    float* Cand = (float*)(smraw + SM_CAND);
    __nv_bfloat16* As = (__nv_bfloat16*)(smraw + SM_A);

    const int tid  = threadIdx.x;
    const int lane = tid & 31;
    const int w    = tid >> 5;
    const int pass = blockIdx.x >> 6;
    const int rowBlock = blockIdx.x & 63;
    const int rowBase  = rowBlock * BM;
    const __nv_bfloat16* Asrc = g_bf + (size_t)pass       * NROWS * DIM;
    const __nv_bfloat16* Bsrc = g_bf + (size_t)(1 - pass) * NROWS * DIM;

    // persistent A rows (128 x 256)
    {
        const uint4* src = (const uint4*)(Asrc + (size_t)rowBase * DIM);
        for (int idx = tid; idx < BM * (DIM / 8); idx += NTH) {
            int r = idx >> 5, c = idx & 31;
            *(uint4*)&As[r * STR + c * 8] = src[r * 32 + c];
        }
    }
    for (int i = tid; i < 128 * 33; i += NTH) Tk[i] = -INFINITY;
    if (tid < 128) Cnt[tid] = 0;

    // prefetch B panel 0
    {
        const char* src = (const char*)(Bsrc);
        #pragma unroll
        for (int i = 0; i < 8; ++i) {
            int idx = tid + i * NTH;             // 2048 uint4 per panel
            int r = idx >> 5, c = idx & 31;
            cp_async16(smb + SM_B0 + (uint32_t)(r * STR + c * 8) * 2u, src + idx * 16);
        }
        CP_COMMIT();
    }

    // ldmatrix lane addressing
    const int aRow     = w * 16 + (lane & 8) + (lane & 7);
    const int aColHalf = (lane & 16) ? 8 : 0;
    const int bRowOff  = ((lane & 16) ? 8 : 0) + (lane & 7);
    const int bColHalf = (lane & 8) ? 8 : 0;
    const uint32_t smA = smb + SM_A;

    const int mrow0 = w * 16 + (lane >> 2);       // rows owned by this thread
    const int nSub  = (lane & 3) * 2;             // col offset within 8-col group
    const int grow0 = rowBase + mrow0;
    const int grow1 = grow0 + 8;
    const int diagP0 = grow0 >> 6;                // panel containing row0's diagonal
    const int diagP1 = grow1 >> 6;

    float acc[8][4];
    #pragma unroll
    for (int nt = 0; nt < 8; ++nt)
        #pragma unroll
        for (int q = 0; q < 4; ++q) acc[nt][q] = 0.0f;

    __syncthreads();

    #pragma unroll 1
    for (int p = 0; p < NPANEL; ++p) {
        const int s = p & 1;
        const uint32_t smB = smb + (s ? SM_B1 : SM_B0);

        // prefetch next panel into the other buffer
        if (p + 1 < NPANEL) {
            const char* src = (const char*)(Bsrc + (size_t)(p + 1) * BN * DIM);
            const uint32_t dst = smb + ((p + 1) & 1 ? SM_B1 : SM_B0);
            #pragma unroll
            for (int i = 0; i < 8; ++i) {
                int idx = tid + i * NTH;
                int r = idx >> 5, c = idx & 31;
                cp_async16(dst + (uint32_t)(r * STR + c * 8) * 2u, src + idx * 16);
            }
            CP_COMMIT();
            CP_WAIT(1);          // current panel's group complete
        } else {
            CP_WAIT(0);
        }
        __syncthreads();

        // ---- 128x64x256 GEMM ----
        #pragma unroll 1
        for (int ks = 0; ks < DIM / 16; ++ks) {
            uint32_t a0, a1, a2, a3;
            ldsm4(a0, a1, a2, a3,
                  smA + (uint32_t)(aRow * STR + ks * 16 + aColHalf) * 2u);
            #pragma unroll
            for (int ntp = 0; ntp < 4; ++ntp) {
                uint32_t b0, b1, b2, b3;
                ldsm4(b0, b1, b2, b3,
                      smB + (uint32_t)((ntp * 16 + bRowOff) * STR + ks * 16 + bColHalf) * 2u);
                mma16816(acc[2 * ntp],     a0, a1, a2, a3, b0, b1);
                mma16816(acc[2 * ntp + 1], a0, a1, a2, a3, b2, b3);
            }
        }

        // ---- register-level filter + rare push ----
        const int colBase = p * BN;
        {
            // row 0 of the pair
            float thr = Tk[mrow0 * 33 + 31];
            float mx = -INFINITY;
            #pragma unroll
            for (int nt = 0; nt < 8; ++nt) mx = fmaxf(mx, fmaxf(acc[nt][0], acc[nt][1]));
            if (mx > thr || p == diagP0) {
                #pragma unroll
                for (int nt = 0; nt < 8; ++nt)
                    #pragma unroll
                    for (int e = 0; e < 2; ++e) {
                        float val = acc[nt][e];
                        int col = colBase + nt * 8 + nSub + e;
                        if (p == diagP0 && col == grow0) { Ps[mrow0] = val; continue; }
                        if (val > thr) {
                            unsigned idx = atomicAdd(&Cnt[mrow0], 1u);
                            Cand[mrow0 * 69 + idx] = val;
                        }
                    }
            }
            // row 1 (mrow0 + 8)
            float thr1 = Tk[(mrow0 + 8) * 33 + 31];
            float mx1 = -INFINITY;
            #pragma unroll
            for (int nt = 0; nt < 8; ++nt) mx1 = fmaxf(mx1, fmaxf(acc[nt][2], acc[nt][3]));
            if (mx1 > thr1 || p == diagP1) {
                #pragma unroll
                for (int nt = 0; nt < 8; ++nt)
                    #pragma unroll
                    for (int e = 0; e < 2; ++e) {
                        float val = acc[nt][2 + e];
                        int col = colBase + nt * 8 + nSub + e;
                        if (p == diagP1 && col == grow1) { Ps[mrow0 + 8] = val; continue; }
                        if (val > thr1) {
                            unsigned idx = atomicAdd(&Cnt[mrow0 + 8], 1u);
                            Cand[(mrow0 + 8) * 69 + idx] = val;
                        }
                    }
            }
        }
        // zero accumulators
        #pragma unroll
        for (int nt = 0; nt < 8; ++nt)
            #pragma unroll
            for (int q = 0; q < 4; ++q) acc[nt][q] = 0.0f;

        __syncthreads();   // pushes visible to merge threads

        // ---- merge candidates into sorted top-32 (thread = row) ----
        if (tid < BM) {
            int c = (int)Cnt[tid];
            if (c > 0) {
                float* tk = Tk + tid * 33;
                float thr = tk[31];
                for (int i = 0; i < c; ++i) {
                    float val = Cand[tid * 69 + i];
                    if (val > thr) {
                        int ip = 31;
                        while (ip > 0 && tk[ip - 1] < val) { tk[ip] = tk[ip - 1]; --ip; }
                        tk[ip] = val;
                        thr = tk[31];
                    }
                }
                Cnt[tid] = 0;
            }
        }
        __syncthreads();   // merged thr + cleared counts visible; B buffer reusable
    }

    // ---- per-row loss ----
    if (tid < BM) {
        const float invT = 1.0f / 0.07f;
        const float* tk = Tk + tid * 33;
        float pp = Ps[tid] * invT;
        float m = fmaxf(pp, tk[0] * invT);
        float s = expf(pp - m);
        #pragma unroll
        for (int i = 0; i < 32; ++i) s += expf(tk[i] * invT - m);
        Rl[tid] = m + logf(s) - pp;
    }
    __syncthreads();
    if (tid == 0) {
        float sum = 0.0f;
        for (int r = 0; r < BM; ++r) sum += Rl[r];   // fixed order: deterministic
        g_partial[blockIdx.x] = sum;
    }
}

__global__ void finalize_kernel(float* out) {
    if (threadIdx.x == 0) {
        float sum = 0.0f;
        for (int i = 0; i < 128; ++i) sum += g_partial[i];
        out[0] = sum * (0.5f / (float)NROWS);
    }
}

extern "C" void kernel_launch(void* const* d_in, const int* in_sizes, int n_in,
                              void* d_out, int out_size) {
    const float* img = (const float*)d_in[0];
    const float* cur = (const float*)d_in[1];
    float* out = (float*)d_out;

    const int cthreads = 2 * NROWS * DIM / 4;
    convert_kernel<<<(cthreads + 255) / 256, 256>>>(img, cur);

    cudaFuncSetAttribute(pass_kernel, cudaFuncAttributeMaxDynamicSharedMemorySize, SM_TOTAL);
    pass_kernel<<<128, NTH, SM_TOTAL>>>();
    finalize_kernel<<<1, 1>>>(out);
}

// round 5
// speedup vs baseline: 6.9396x; 1.0421x over previous
#include <cuda_runtime.h>
#include <cuda_bf16.h>
#include <math.h>
#include <stdint.h>

// ---------------------------------------------------------------------------
// HardNegativeContrastiveLoss N=8192 D=256. Round 5: mma.sync bf16 GEMM,
// 512 threads (4 warps/SMSP for latency hiding), N-split warp layout,
// register-level top-k filter, cp.async double-buffered B panels.
// Both directions in one 128-CTA wave. Logits never touch HBM.
// ---------------------------------------------------------------------------

#define NROWS 8192
#define DIM   256
#define BM    128
#define BN    64
#define NTH   512
#define NPANEL (NROWS / BN)     // 128
#define STR   264               // bf16 elems per SMEM row (528 B, LDSM conflict-free)

// ---- SMEM byte offsets ----
#define SM_TK    0                        // 128 x 33 f32 sorted desc top-32
#define SM_CNT   16896                    // 128 u32 candidate counts
#define SM_PS    17408                    // 128 f32 positives
#define SM_RL    17920                    // 128 f32 row losses
#define SM_CAND  18432                    // 128 x 69 f32 candidates
#define SM_A     53760                    // 128 x 264 bf16  (67584 B)
#define SM_B0    121344                   // 64 x 264 bf16   (33792 B)
#define SM_B1    155136
#define SM_TOTAL 188928

__device__ __nv_bfloat16 g_bf[2 * NROWS * DIM];
__device__ float g_partial[128];

// ---- fp32 -> bf16 conversion ----------------------------------------------
__global__ void convert_kernel(const float* __restrict__ a, const float* __restrict__ b) {
    int i = blockIdx.x * blockDim.x + threadIdx.x;
    const int n = NROWS * DIM / 4;
    if (i < n) {
        float4 v = ((const float4*)a)[i];
        __nv_bfloat162* o = (__nv_bfloat162*)(g_bf) + i * 2;
        o[0] = __floats2bfloat162_rn(v.x, v.y);
        o[1] = __floats2bfloat162_rn(v.z, v.w);
    } else if (i < 2 * n) {
        int j = i - n;
        float4 v = ((const float4*)b)[j];
        __nv_bfloat162* o = (__nv_bfloat162*)(g_bf + NROWS * DIM) + j * 2;
        o[0] = __floats2bfloat162_rn(v.x, v.y);
        o[1] = __floats2bfloat162_rn(v.z, v.w);
    }
}

// ---- PTX helpers ----------------------------------------------------------
__device__ __forceinline__ void ldsm4(uint32_t& r0, uint32_t& r1, uint32_t& r2, uint32_t& r3,
                                      uint32_t addr) {
    asm volatile("ldmatrix.sync.aligned.m8n8.x4.shared.b16 {%0,%1,%2,%3}, [%4];"
                 : "=r"(r0), "=r"(r1), "=r"(r2), "=r"(r3) : "r"(addr));
}
__device__ __forceinline__ void mma16816(float* c,
                                         uint32_t a0, uint32_t a1, uint32_t a2, uint32_t a3,
                                         uint32_t b0, uint32_t b1) {
    asm volatile("mma.sync.aligned.m16n8k16.row.col.f32.bf16.bf16.f32 "
                 "{%0,%1,%2,%3}, {%4,%5,%6,%7}, {%8,%9}, {%0,%1,%2,%3};"
                 : "+f"(c[0]), "+f"(c[1]), "+f"(c[2]), "+f"(c[3])
                 : "r"(a0), "r"(a1), "r"(a2), "r"(a3), "r"(b0), "r"(b1));
}
__device__ __forceinline__ void cp_async16(uint32_t smem_addr, const void* gptr) {
    asm volatile("cp.async.cg.shared.global [%0], [%1], 16;"
                 :: "r"(smem_addr), "l"(gptr));
}
#define CP_COMMIT() asm volatile("cp.async.commit_group;" ::: "memory")
#define CP_WAIT(N)  asm volatile("cp.async.wait_group " #N ";" ::: "memory")

// ---- fused GEMM + top-32 + loss -------------------------------------------
__global__ __launch_bounds__(NTH, 1)
void pass_kernel() {
    extern __shared__ char smraw[];
    const uint32_t smb = (uint32_t)__cvta_generic_to_shared(smraw);
    float* Tk     = (float*)(smraw + SM_TK);
    unsigned* Cnt = (unsigned*)(smraw + SM_CNT);
    float* Ps     = (float*)(smraw + SM_PS);
    float* Rl     = (float*)(smraw + SM_RL);
    float* Cand   = (float*)(smraw + SM_CAND);
    __nv_bfloat16* As = (__nv_bfloat16*)(smraw + SM_A);

    const int tid  = threadIdx.x;
    const int lane = tid & 31;
    const int wid  = tid >> 5;
    const int mW   = wid & 7;              // m-tile: rows [16*mW, 16*mW+16)
    const int nG   = wid >> 3;             // n-group: cols [32*nG, 32*nG+32) of panel
    const int pass = blockIdx.x >> 6;
    const int rowBlock = blockIdx.x & 63;
    const int rowBase  = rowBlock * BM;
    const __nv_bfloat16* Asrc = g_bf + (size_t)pass       * NROWS * DIM;
    const __nv_bfloat16* Bsrc = g_bf + (size_t)(1 - pass) * NROWS * DIM;

    // persistent A rows (128 x 256)
    {
        const uint4* src = (const uint4*)(Asrc + (size_t)rowBase * DIM);
        #pragma unroll
        for (int i = 0; i < 8; ++i) {
            int idx = tid + i * NTH;       // 4096 uint4 total
            int r = idx >> 5, c = idx & 31;
            *(uint4*)&As[r * STR + c * 8] = src[r * 32 + c];
        }
    }
    for (int i = tid; i < 128 * 33; i += NTH) Tk[i] = -INFINITY;
    if (tid < 128) Cnt[tid] = 0;

    // prefetch B panel 0 (2048 uint4)
    {
        const char* src = (const char*)(Bsrc);
        #pragma unroll
        for (int i = 0; i < 4; ++i) {
            int idx = tid + i * NTH;
            int r = idx >> 5, c = idx & 31;
            cp_async16(smb + SM_B0 + (uint32_t)(r * STR + c * 8) * 2u, src + idx * 16);
        }
        CP_COMMIT();
    }

    // ldmatrix lane addressing
    const int aRow     = mW * 16 + (lane & 8) + (lane & 7);
    const int aColHalf = (lane & 16) ? 8 : 0;
    const int bRowOff  = ((lane & 16) ? 8 : 0) + (lane & 7);
    const int bColHalf = (lane & 8) ? 8 : 0;
    const uint32_t smA = smb + SM_A;

    const int mrow0 = mW * 16 + (lane >> 2);   // rows owned by this thread
    const int nSub  = (lane & 3) * 2;
    const int grow0 = rowBase + mrow0;
    const int grow1 = grow0 + 8;
    const int diagP0 = grow0 >> 6;             // panel holding row's diagonal
    const int diagP1 = grow1 >> 6;

    float acc[4][4];
    #pragma unroll
    for (int nt = 0; nt < 4; ++nt)
        #pragma unroll
        for (int q = 0; q < 4; ++q) acc[nt][q] = 0.0f;

    __syncthreads();

    #pragma unroll 1
    for (int p = 0; p < NPANEL; ++p) {
        const int s = p & 1;
        const uint32_t smB = smb + (s ? SM_B1 : SM_B0);

        // prefetch next panel into the other buffer
        if (p + 1 < NPANEL) {
            const char* src = (const char*)(Bsrc + (size_t)(p + 1) * BN * DIM);
            const uint32_t dst = smb + ((p + 1) & 1 ? SM_B1 : SM_B0);
            #pragma unroll
            for (int i = 0; i < 4; ++i) {
                int idx = tid + i * NTH;
                int r = idx >> 5, c = idx & 31;
                cp_async16(dst + (uint32_t)(r * STR + c * 8) * 2u, src + idx * 16);
            }
            CP_COMMIT();
            CP_WAIT(1);
        } else {
            CP_WAIT(0);
        }
        __syncthreads();

        // ---- m16n32 x k256 per warp ----
        #pragma unroll 1
        for (int ks = 0; ks < DIM / 16; ++ks) {
            uint32_t a0, a1, a2, a3;
            ldsm4(a0, a1, a2, a3,
                  smA + (uint32_t)(aRow * STR + ks * 16 + aColHalf) * 2u);
            #pragma unroll
            for (int ntp = 0; ntp < 2; ++ntp) {
                uint32_t b0, b1, b2, b3;
                ldsm4(b0, b1, b2, b3,
                      smB + (uint32_t)((nG * 32 + ntp * 16 + bRowOff) * STR + ks * 16 + bColHalf) * 2u);
                mma16816(acc[2 * ntp],     a0, a1, a2, a3, b0, b1);
                mma16816(acc[2 * ntp + 1], a0, a1, a2, a3, b2, b3);
            }
        }

        // ---- register-level filter + rare push ----
        const int colBase = p * BN + nG * 32;
        {
            float thr = Tk[mrow0 * 33 + 31];
            float mx = -INFINITY;
            #pragma unroll
            for (int nt = 0; nt < 4; ++nt) mx = fmaxf(mx, fmaxf(acc[nt][0], acc[nt][1]));
            if (mx > thr || p == diagP0) {
                #pragma unroll
                for (int nt = 0; nt < 4; ++nt)
                    #pragma unroll
                    for (int e = 0; e < 2; ++e) {
                        float val = acc[nt][e];
                        int col = colBase + nt * 8 + nSub + e;
                        if (p == diagP0 && col == grow0) { Ps[mrow0] = val; continue; }
                        if (val > thr) {
                            unsigned idx = atomicAdd(&Cnt[mrow0], 1u);
                            Cand[mrow0 * 69 + idx] = val;
                        }
                    }
            }
            float thr1 = Tk[(mrow0 + 8) * 33 + 31];
            float mx1 = -INFINITY;
            #pragma unroll
            for (int nt = 0; nt < 4; ++nt) mx1 = fmaxf(mx1, fmaxf(acc[nt][2], acc[nt][3]));
            if (mx1 > thr1 || p == diagP1) {
                #pragma unroll
                for (int nt = 0; nt < 4; ++nt)
                    #pragma unroll
                    for (int e = 0; e < 2; ++e) {
                        float val = acc[nt][2 + e];
                        int col = colBase + nt * 8 + nSub + e;
                        if (p == diagP1 && col == grow1) { Ps[mrow0 + 8] = val; continue; }
                        if (val > thr1) {
                            unsigned idx = atomicAdd(&Cnt[mrow0 + 8], 1u);
                            Cand[(mrow0 + 8) * 69 + idx] = val;
                        }
                    }
            }
        }
        #pragma unroll
        for (int nt = 0; nt < 4; ++nt)
            #pragma unroll
            for (int q = 0; q < 4; ++q) acc[nt][q] = 0.0f;

        __syncthreads();   // pushes visible to merge threads

        // ---- merge candidates into sorted top-32 (thread = row) ----
        if (tid < BM) {
            int c = (int)Cnt[tid];
            if (c > 0) {
                float* tk = Tk + tid * 33;
                float thr = tk[31];
                for (int i = 0; i < c; ++i) {
                    float val = Cand[tid * 69 + i];
                    if (val > thr) {
                        int ip = 31;
                        while (ip > 0 && tk[ip - 1] < val) { tk[ip] = tk[ip - 1]; --ip; }
                        tk[ip] = val;
                        thr = tk[31];
                    }
                }
                Cnt[tid] = 0;
            }
        }
        __syncthreads();   // merged thr + cleared counts visible; B buffer reusable
    }

    // ---- per-row loss ----
    if (tid < BM) {
        const float invT = 1.0f / 0.07f;
        const float* tk = Tk + tid * 33;
        float pp = Ps[tid] * invT;
        float m = fmaxf(pp, tk[0] * invT);
        float s = expf(pp - m);
        #pragma unroll
        for (int i = 0; i < 32; ++i) s += expf(tk[i] * invT - m);
        Rl[tid] = m + logf(s) - pp;
    }
    __syncthreads();
    if (tid == 0) {
        float sum = 0.0f;
        for (int r = 0; r < BM; ++r) sum += Rl[r];   // fixed order: deterministic
        g_partial[blockIdx.x] = sum;
    }
}

__global__ void finalize_kernel(float* out) {
    if (threadIdx.x == 0) {
        float sum = 0.0f;
        for (int i = 0; i < 128; ++i) sum += g_partial[i];
        out[0] = sum * (0.5f / (float)NROWS);
    }
}

extern "C" void kernel_launch(void* const* d_in, const int* in_sizes, int n_in,
                              void* d_out, int out_size) {
    const float* img = (const float*)d_in[0];
    const float* cur = (const float*)d_in[1];
    float* out = (float*)d_out;

    const int cthreads = 2 * NROWS * DIM / 4;
    convert_kernel<<<(cthreads + 255) / 256, 256>>>(img, cur);

    cudaFuncSetAttribute(pass_kernel, cudaFuncAttributeMaxDynamicSharedMemorySize, SM_TOTAL);
    pass_kernel<<<128, NTH, SM_TOTAL>>>();
    finalize_kernel<<<1, 1>>>(out);
}